// round 5
// baseline (speedup 1.0000x reference)
#include <cuda_runtime.h>
#include <cuda_bf16.h>
#include <math.h>

#define S      512
#define BATCH  64
#define TLEN   1024
#define OBS_N  32000

#define I_SM     192            // expT rows cached in SMEM
#define G_ROWS   (S - I_SM)     // 320 rows streamed from L2
#define NTHREADS 256
#define LOG2E 1.4426950408889634f
#define LN2   0.6931471805599453f

// ---------------- device scratch (allowed: __device__ globals) --------------
__device__ float g_lseRow[S];                 // logsumexp of state_transitions rows
__device__ float g_mT[S];                     // column max of log_trans
__device__ float g_lseObs[S];                 // logsumexp of obs rows
__device__ float g_Cfold[S];                  // mT - lseObs
__device__ float g_initAdd[S];                // log_prior - lseObs
__device__ __nv_bfloat16 g_expT[S * S];       // exp(logT - mT[j]), row-major [i][j]

// ---------------- helpers ---------------------------------------------------
__device__ __forceinline__ __nv_bfloat162 u2bf2(unsigned u) {
    __nv_bfloat162 r;
    *reinterpret_cast<unsigned*>(&r) = u;
    return r;
}

template <int NW>
__device__ __forceinline__ float blkMax(float v, float* red) {
    #pragma unroll
    for (int o = 16; o > 0; o >>= 1) v = fmaxf(v, __shfl_xor_sync(0xffffffffu, v, o));
    int w = threadIdx.x >> 5;
    if ((threadIdx.x & 31) == 0) red[w] = v;
    __syncthreads();
    float m = red[0];
    #pragma unroll
    for (int k = 1; k < NW; ++k) m = fmaxf(m, red[k]);
    __syncthreads();
    return m;
}

template <int NW>
__device__ __forceinline__ float blkSum(float v, float* red) {
    #pragma unroll
    for (int o = 16; o > 0; o >>= 1) v += __shfl_xor_sync(0xffffffffu, v, o);
    int w = threadIdx.x >> 5;
    if ((threadIdx.x & 31) == 0) red[w] = v;
    __syncthreads();
    float m = 0.f;
    #pragma unroll
    for (int k = 0; k < NW; ++k) m += red[k];
    __syncthreads();
    return m;
}

// ---------------- precompute kernels ----------------------------------------

// logsumexp of each state_transitions row (512 elems). grid=S, block=256.
__global__ void k_rowlse(const float* __restrict__ ST) {
    __shared__ float red[8];
    int i = blockIdx.x, t = threadIdx.x;
    float x0 = ST[i * S + t];
    float x1 = ST[i * S + t + 256];
    float M = blkMax<8>(fmaxf(x0, x1), red);
    float s = expf(x0 - M) + expf(x1 - M);
    float Ssum = blkSum<8>(s, red);
    if (t == 0) g_lseRow[i] = M + logf(Ssum);
}

// column max of log_trans. grid=4, block=128.
__global__ void k_colmax(const float* __restrict__ ST) {
    int j = blockIdx.x * blockDim.x + threadIdx.x;
    float m = -1e30f;
    for (int i = 0; i < S; ++i)
        m = fmaxf(m, ST[i * S + j] - g_lseRow[i]);
    g_mT[j] = m;
}

// expT[i][j] = exp(logT - mT[j]) as bf16. grid=S, block=256.
__global__ void k_expT(const float* __restrict__ ST) {
    int i = blockIdx.x;
    int j = threadIdx.x * 2;
    float l = g_lseRow[i];
    float v0 = expf(ST[i * S + j]     - l - g_mT[j]);
    float v1 = expf(ST[i * S + j + 1] - l - g_mT[j + 1]);
    g_expT[i * S + j]     = __float2bfloat16(v0);
    g_expT[i * S + j + 1] = __float2bfloat16(v1);
}

// logsumexp of each obs row (32000 elems) + Cfold. grid=S, block=256.
__global__ void k_obslse(const float* __restrict__ OT) {
    __shared__ float red[8];
    int s = blockIdx.x, t = threadIdx.x;
    const float* row = OT + (size_t)s * OBS_N;
    float m = -1e30f;
    for (int k = t; k < OBS_N; k += 256) m = fmaxf(m, row[k]);
    float M = blkMax<8>(m, red);
    float acc = 0.f;
    for (int k = t; k < OBS_N; k += 256) acc += expf(row[k] - M);
    float Ssum = blkSum<8>(acc, red);
    if (t == 0) {
        float lse = M + logf(Ssum);
        g_lseObs[s] = lse;
        g_Cfold[s]  = g_mT[s] - lse;
    }
}

// log_softmax(prior) - lseObs. grid=1, block=512.
__global__ void k_prior(const float* __restrict__ prior) {
    __shared__ float red[16];
    int t = threadIdx.x;
    float p = prior[t];
    float M = blkMax<16>(p, red);
    float Ssum = blkSum<16>(expf(p - M), red);
    float lse = M + logf(Ssum);
    g_initAdd[t] = (p - lse) - g_lseObs[t];
}

// ---------------- main forward kernel ----------------------------------------
// SMEM layout (bytes):
//   [0,      196608) expT rows [0,192)  (bf16 [192][512])
//   [196608, 204800) Pscr f32 [4][512]
//   [204800, 206848) aRep bf16x2 [512] (value replicated in both halves)
//   [206848, 208896) Cfold f32 [512]
//   [208896, 212992) obs int [1024]
//   [212992, 213120) reduction scratch
#define SMEM_TOTAL 213120

__global__ void __launch_bounds__(NTHREADS, 1)
k_forward(const int* __restrict__ obs, const float* __restrict__ OT,
          float* __restrict__ out) {
    extern __shared__ char smem[];
    __nv_bfloat16*  sT   = reinterpret_cast<__nv_bfloat16*>(smem);
    float*          sP   = reinterpret_cast<float*>(smem + 196608);
    __nv_bfloat162* sA   = reinterpret_cast<__nv_bfloat162*>(smem + 204800);
    float*          sCf  = reinterpret_cast<float*>(smem + 206848);
    int*            sOb  = reinterpret_cast<int*>(smem + 208896);
    float*          sRed = reinterpret_cast<float*>(smem + 212992);

    const int b = blockIdx.x, t = threadIdx.x;

    // one-time loads: expT cache (step-invariant), Cfold, this batch's obs
    {
        const uint4* src = reinterpret_cast<const uint4*>(g_expT);
        uint4* dst = reinterpret_cast<uint4*>(sT);
        const int n = I_SM * S * 2 / 16;   // 12288 uint4
        for (int k = t; k < n; k += NTHREADS) dst[k] = src[k];
    }
    for (int k = t; k < S; k += NTHREADS)    sCf[k] = g_Cfold[k];
    for (int k = t; k < TLEN; k += NTHREADS) sOb[k] = obs[b * TLEN + k];
    __syncthreads();

    const int oct = t & 63;   // matvec role: j-oct (8 consecutive j)
    const int iq  = t >> 6;   // matvec role: i-quarter
    const int j0  = t * 2;    // epilogue role: j pair

    // ---- init: alpha0 = W[:,o0] + (log_prior - lseObs) ----
    float E2;  // running log2 offset (identical in all threads)
    {
        int o0 = sOb[0];
        float a0 = __ldg(OT + (size_t)j0 * OBS_N + o0)       + g_initAdd[j0];
        float a1 = __ldg(OT + (size_t)(j0 + 1) * OBS_N + o0) + g_initAdd[j0 + 1];
        float M = blkMax<8>(fmaxf(a0, a1), sRed);
        E2 = M * LOG2E;
        sA[j0]     = __bfloat162bfloat162(__float2bfloat16(exp2f((a0 - M) * LOG2E)));
        sA[j0 + 1] = __bfloat162bfloat162(__float2bfloat16(exp2f((a1 - M) * LOG2E)));
    }
    __syncthreads();

    const __nv_bfloat16* gT = g_expT + (size_t)I_SM * S;
    const int sBase = iq * 48;   // 48 SMEM rows per i-quarter (3 chunks of 16)
    const int gBase = iq * 80;   // 80 global rows per i-quarter (5 chunks of 16)
    float fin0 = 0.f, fin1 = 0.f;
    const __nv_bfloat162 z = __float2bfloat162_rn(0.f);

    for (int step = 1; step <= TLEN; ++step) {
        const int ot = (step < TLEN) ? sOb[step] : 0;   // terminal obs = 0
        // prefetch obs column for this step's epilogue (consumed ~4000 cyc later)
        const float w0 = __ldg(OT + (size_t)j0 * OBS_N + ot);
        const float w1 = __ldg(OT + (size_t)(j0 + 1) * OBS_N + ot);

        float facc[8];
        #pragma unroll
        for (int k = 0; k < 8; ++k) facc[k] = 0.f;

        // ---- matvec, SMEM-resident rows ----
        #pragma unroll 1
        for (int c = 0; c < 3; ++c) {
            __nv_bfloat162 ac0 = z, ac1 = z, ac2 = z, ac3 = z;
            const int ib = sBase + c * 16;
            #pragma unroll
            for (int u = 0; u < 4; ++u) {
                const int i = ib + u * 4;
                uint4 av = *reinterpret_cast<const uint4*>(sA + i);  // a[i..i+3] (broadcast)
                unsigned avv[4] = {av.x, av.y, av.z, av.w};
                #pragma unroll
                for (int r = 0; r < 4; ++r) {
                    uint4 e = *reinterpret_cast<const uint4*>(sT + (i + r) * S + oct * 8);
                    __nv_bfloat162 a = u2bf2(avv[r]);
                    ac0 = __hfma2(a, u2bf2(e.x), ac0);
                    ac1 = __hfma2(a, u2bf2(e.y), ac1);
                    ac2 = __hfma2(a, u2bf2(e.z), ac2);
                    ac3 = __hfma2(a, u2bf2(e.w), ac3);
                }
            }
            facc[0] += __low2float(ac0); facc[1] += __high2float(ac0);
            facc[2] += __low2float(ac1); facc[3] += __high2float(ac1);
            facc[4] += __low2float(ac2); facc[5] += __high2float(ac2);
            facc[6] += __low2float(ac3); facc[7] += __high2float(ac3);
        }
        // ---- matvec, L2-streamed rows ----
        #pragma unroll 1
        for (int c = 0; c < 5; ++c) {
            __nv_bfloat162 ac0 = z, ac1 = z, ac2 = z, ac3 = z;
            const int ib = gBase + c * 16;
            #pragma unroll
            for (int u = 0; u < 4; ++u) {
                const int gi = ib + u * 4;
                uint4 av = *reinterpret_cast<const uint4*>(sA + I_SM + gi);
                unsigned avv[4] = {av.x, av.y, av.z, av.w};
                #pragma unroll
                for (int r = 0; r < 4; ++r) {
                    uint4 e = __ldg(reinterpret_cast<const uint4*>(
                        gT + (size_t)(gi + r) * S + oct * 8));
                    __nv_bfloat162 a = u2bf2(avv[r]);
                    ac0 = __hfma2(a, u2bf2(e.x), ac0);
                    ac1 = __hfma2(a, u2bf2(e.y), ac1);
                    ac2 = __hfma2(a, u2bf2(e.z), ac2);
                    ac3 = __hfma2(a, u2bf2(e.w), ac3);
                }
            }
            facc[0] += __low2float(ac0); facc[1] += __high2float(ac0);
            facc[2] += __low2float(ac1); facc[3] += __high2float(ac1);
            facc[4] += __low2float(ac2); facc[5] += __high2float(ac2);
            facc[6] += __low2float(ac3); facc[7] += __high2float(ac3);
        }

        // ---- cross-i-quarter reduction via SMEM ----
        {
            float2* ps = reinterpret_cast<float2*>(sP + iq * S + oct * 8);
            ps[0] = make_float2(facc[0], facc[1]);
            ps[1] = make_float2(facc[2], facc[3]);
            ps[2] = make_float2(facc[4], facc[5]);
            ps[3] = make_float2(facc[6], facc[7]);
        }
        __syncthreads();
        float p0 = 0.f, p1 = 0.f;
        #pragma unroll
        for (int q = 0; q < 4; ++q) {
            float2 v = *reinterpret_cast<const float2*>(sP + q * S + j0);
            p0 += v.x; p1 += v.y;
        }

        // ---- epilogue: a'[j] = P[j] * exp2((W - lseObs + mT)*log2e), then
        //      exact power-of-two renormalization (m2 integer, 2^-m2 exact) ----
        float raw0 = p0 * exp2f((w0 + sCf[j0])     * LOG2E);
        float raw1 = p1 * exp2f((w1 + sCf[j0 + 1]) * LOG2E);
        float M2 = blkMax<8>(fmaxf(raw0, raw1), sRed);
        M2 = fmaxf(M2, 1e-30f);
        int   m2  = (__float_as_int(M2) >> 23) - 127;
        float scl = __int_as_float((127 - m2) << 23);
        E2 += (float)m2;
        fin0 = raw0 * scl;
        fin1 = raw1 * scl;
        sA[j0]     = __bfloat162bfloat162(__float2bfloat16(fin0));
        sA[j0 + 1] = __bfloat162bfloat162(__float2bfloat16(fin1));
        __syncthreads();
    }

    // ---- final: out[b] = log(sum a) + E2*ln2 ----
    float total = blkSum<8>(fin0 + fin1, sRed);
    if (t == 0) out[b] = logf(total) + E2 * LN2;
}

// ---------------- launch ------------------------------------------------------
extern "C" void kernel_launch(void* const* d_in, const int* in_sizes, int n_in,
                              void* d_out, int out_size) {
    const int*   obs   = (const int*)d_in[0];     // [64,1024] int32
    const float* ST    = (const float*)d_in[1];   // [512,512]
    const float* OT    = (const float*)d_in[2];   // [512,32000]
    const float* prior = (const float*)d_in[3];   // [512]
    float* out = (float*)d_out;                   // [64] f32

    cudaFuncSetAttribute(k_forward, cudaFuncAttributeMaxDynamicSharedMemorySize,
                         SMEM_TOTAL);

    k_rowlse<<<S, 256>>>(ST);
    k_colmax<<<4, 128>>>(ST);
    k_expT<<<S, 256>>>(ST);
    k_obslse<<<S, 256>>>(OT);
    k_prior<<<1, S>>>(prior);
    k_forward<<<BATCH, NTHREADS, SMEM_TOTAL>>>(obs, OT, out);
}

// round 7
// speedup vs baseline: 1.8237x; 1.8237x over previous
#include <cuda_runtime.h>
#include <cuda_bf16.h>
#include <cstdint>
#include <math.h>

#define S      512
#define BATCH  64
#define TLEN   1024
#define OBS_N  32000
#define NTHREADS 256
#define JH     256              // j-columns per CTA (cluster of 2)
#define SMG    40               // SMEM rows per 64-row i-group
#define SM_ROWS (8 * SMG)       // 320 rows resident in SMEM
#define REG_ROWS 24             // register-resident rows per thread (per i-group)
#define LOG2E 1.4426950408889634f
#define LN2   0.6931471805599453f

// ---------------- device scratch ---------------------------------------------
__device__ float g_lseRow[S];
__device__ float g_mT[S];
__device__ float g_lseObs[S];
__device__ float g_Cfold[S];                 // mT - lseObs
__device__ float g_initAdd[S];               // log_softmax(prior) - lseObs
// expT rearranged per j-half: [rank][i][256] bf16
__device__ __nv_bfloat16 g_expT2[2 * S * JH];

// ---------------- helpers -----------------------------------------------------
__device__ __forceinline__ __nv_bfloat162 u2bf2(unsigned u) {
    __nv_bfloat162 r; *reinterpret_cast<unsigned*>(&r) = u; return r;
}
__device__ __forceinline__ uint32_t smem_u32(const void* p) {
    uint32_t a;
    asm("{ .reg .u64 t; cvta.to.shared.u64 t, %1; cvt.u32.u64 %0, t; }"
        : "=r"(a) : "l"(p));
    return a;
}
__device__ __forceinline__ uint32_t mapa_u32(uint32_t a, uint32_t rank) {
    uint32_t d;
    asm("mapa.shared::cluster.u32 %0, %1, %2;" : "=r"(d) : "r"(a), "r"(rank));
    return d;
}
__device__ __forceinline__ void st_cluster_f32(uint32_t a, float v) {
    asm volatile("st.shared::cluster.f32 [%0], %1;" :: "r"(a), "f"(v) : "memory");
}
#define CLUSTER_SYNC() do { \
    asm volatile("barrier.cluster.arrive.aligned;" ::: "memory"); \
    asm volatile("barrier.cluster.wait.aligned;"   ::: "memory"); \
} while (0)

template <int NW>
__device__ __forceinline__ float blkMax(float v, float* red) {
    #pragma unroll
    for (int o = 16; o > 0; o >>= 1) v = fmaxf(v, __shfl_xor_sync(0xffffffffu, v, o));
    int w = threadIdx.x >> 5;
    if ((threadIdx.x & 31) == 0) red[w] = v;
    __syncthreads();
    float m = red[0];
    #pragma unroll
    for (int k = 1; k < NW; ++k) m = fmaxf(m, red[k]);
    __syncthreads();
    return m;
}
template <int NW>
__device__ __forceinline__ float blkSum(float v, float* red) {
    #pragma unroll
    for (int o = 16; o > 0; o >>= 1) v += __shfl_xor_sync(0xffffffffu, v, o);
    int w = threadIdx.x >> 5;
    if ((threadIdx.x & 31) == 0) red[w] = v;
    __syncthreads();
    float m = 0.f;
    #pragma unroll
    for (int k = 0; k < NW; ++k) m += red[k];
    __syncthreads();
    return m;
}

// ---------------- precompute kernels ------------------------------------------
__global__ void k_rowlse(const float* __restrict__ ST) {
    __shared__ float red[8];
    int i = blockIdx.x, t = threadIdx.x;
    float x0 = ST[i * S + t], x1 = ST[i * S + t + 256];
    float M = blkMax<8>(fmaxf(x0, x1), red);
    float Ssum = blkSum<8>(expf(x0 - M) + expf(x1 - M), red);
    if (t == 0) g_lseRow[i] = M + logf(Ssum);
}
__global__ void k_colmax(const float* __restrict__ ST) {
    int j = blockIdx.x * blockDim.x + threadIdx.x;
    float m = -1e30f;
    for (int i = 0; i < S; ++i) m = fmaxf(m, ST[i * S + j] - g_lseRow[i]);
    g_mT[j] = m;
}
__global__ void k_expT(const float* __restrict__ ST) {
    int i = blockIdx.x;
    float l = g_lseRow[i];
    for (int j = threadIdx.x; j < S; j += 256) {
        float v = expf(ST[i * S + j] - l - g_mT[j]);
        int rank = j >> 8, c = j & 255;
        g_expT2[((size_t)rank * S + i) * JH + c] = __float2bfloat16(v);
    }
}
__global__ void k_obslse(const float* __restrict__ OT) {
    __shared__ float red[8];
    int s = blockIdx.x, t = threadIdx.x;
    const float* row = OT + (size_t)s * OBS_N;
    float m = -1e30f;
    for (int k = t; k < OBS_N; k += 256) m = fmaxf(m, row[k]);
    float M = blkMax<8>(m, red);
    float acc = 0.f;
    for (int k = t; k < OBS_N; k += 256) acc += expf(row[k] - M);
    float Ssum = blkSum<8>(acc, red);
    if (t == 0) {
        float lse = M + logf(Ssum);
        g_lseObs[s] = lse;
        g_Cfold[s]  = g_mT[s] - lse;
    }
}
__global__ void k_prior(const float* __restrict__ prior) {
    __shared__ float red[16];
    int t = threadIdx.x;
    float p = prior[t];
    float M = blkMax<16>(p, red);
    float Ssum = blkSum<16>(expf(p - M), red);
    float lse = M + logf(Ssum);
    g_initAdd[t] = (p - lse) - g_lseObs[t];
}

// ---------------- forward kernel (cluster of 2, j-split) ----------------------
// SMEM (bytes):
//  [0,163840)        sT    bf16 [320][256]  (permuted rows: k<40 of each 64-group)
//  [163840,172032)   sP    f32 [8][256]
//  [172032,174080)   sA    bf16x2 [512] (replicated halves)
//  [174080,175104)   sCf   f32 [256] (own j-half)
//  [175104,177216)   sRecv f32 [2][264] ([t]=raw, [256]=local max)
//  [177216,181312)   sOb   int [1024]
//  [181312,181440)   sRed
#define SMEM_TOTAL 181440

__global__ void __launch_bounds__(NTHREADS, 1) __cluster_dims__(2, 1, 1)
k_forward(const int* __restrict__ obs, const float* __restrict__ OT,
          float* __restrict__ out) {
    extern __shared__ char smem[];
    __nv_bfloat16*  sT   = reinterpret_cast<__nv_bfloat16*>(smem);
    float*          sP   = reinterpret_cast<float*>(smem + 163840);
    __nv_bfloat162* sA   = reinterpret_cast<__nv_bfloat162*>(smem + 172032);
    float*          sCf  = reinterpret_cast<float*>(smem + 174080);
    float*          sRecv= reinterpret_cast<float*>(smem + 175104);
    int*            sOb  = reinterpret_cast<int*>(smem + 177216);
    float*          sRed = reinterpret_cast<float*>(smem + 181312);

    const int t    = threadIdx.x;
    const int rank = blockIdx.x & 1;           // == cluster rank (cluster_dims 2)
    const int b    = blockIdx.x >> 1;
    const int ig   = t >> 5, oct = t & 31;     // 8 i-groups x 32 j-octs

    const __nv_bfloat16* gT = g_expT2 + (size_t)rank * S * JH;

    // one-time: SMEM copy (permuted: SMEM row g*40+k <- global row g*64+k, k<40)
    {
        const uint4* src = reinterpret_cast<const uint4*>(gT);   // 32 uint4 / row
        uint4* dst = reinterpret_cast<uint4*>(sT);
        for (int idx = t; idx < SM_ROWS * 32; idx += NTHREADS) {
            int r = idx >> 5, c = idx & 31;
            int g = r / SMG, k = r - g * SMG;
            dst[idx] = src[(g * 64 + k) * 32 + c];
        }
    }
    for (int k = t; k < JH; k += NTHREADS)   sCf[k] = g_Cfold[rank * JH + k];
    for (int k = t; k < TLEN; k += NTHREADS) sOb[k] = obs[b * TLEN + k];

    // register-resident rows: global rows ig*64+40 .. ig*64+63 (step-invariant!)
    uint4 eReg[REG_ROWS];
    {
        const int rb = ig * 64 + SMG;
        #pragma unroll
        for (int m = 0; m < REG_ROWS; ++m)
            eReg[m] = __ldg(reinterpret_cast<const uint4*>(
                gT + (size_t)(rb + m) * JH + oct * 8));
    }
    __syncthreads();

    // init: alpha0 over full 512 (redundant in both CTAs -> identical E2 track)
    float E2;
    {
        int o0 = sOb[0];
        int j0 = 2 * t;
        float a0 = __ldg(OT + (size_t)j0 * OBS_N + o0)       + g_initAdd[j0];
        float a1 = __ldg(OT + (size_t)(j0 + 1) * OBS_N + o0) + g_initAdd[j0 + 1];
        float M = blkMax<8>(fmaxf(a0, a1), sRed);
        E2 = M * LOG2E;
        sA[j0]     = __bfloat162bfloat162(__float2bfloat16(exp2f((a0 - M) * LOG2E)));
        sA[j0 + 1] = __bfloat162bfloat162(__float2bfloat16(exp2f((a1 - M) * LOG2E)));
    }
    __syncthreads();

    // DSMEM peer address for the exchange buffer
    const uint32_t recvPeer = mapa_u32(smem_u32(sRecv), (uint32_t)(rank ^ 1));

    const int iBase  = ig * 64;
    const int srBase = ig * SMG;
    const __nv_bfloat162 z = __float2bfloat162_rn(0.f);
    float finSum = 0.f;
    int slot = 0;

    #pragma unroll 1
    for (int step = 1; step <= TLEN; ++step) {
        const int ot = (step < TLEN) ? sOb[step] : 0;            // terminal obs 0
        const float w = __ldg(OT + (size_t)(rank * JH + t) * OBS_N + ot);

        float facc[8];
        #pragma unroll
        for (int k = 0; k < 8; ++k) facc[k] = 0.f;

        // ---- SMEM-resident rows: 2 chunks x 20 ----
        #pragma unroll
        for (int c = 0; c < 2; ++c) {
            __nv_bfloat162 ac0 = z, ac1 = z, ac2 = z, ac3 = z;
            const int i0 = iBase + c * 20, s0 = srBase + c * 20;
            #pragma unroll
            for (int u = 0; u < 5; ++u) {
                uint4 av = *reinterpret_cast<const uint4*>(sA + i0 + u * 4);
                unsigned avv[4] = {av.x, av.y, av.z, av.w};
                #pragma unroll
                for (int r = 0; r < 4; ++r) {
                    uint4 e = *reinterpret_cast<const uint4*>(
                        sT + (size_t)(s0 + u * 4 + r) * JH + oct * 8);
                    __nv_bfloat162 a = u2bf2(avv[r]);
                    ac0 = __hfma2(a, u2bf2(e.x), ac0);
                    ac1 = __hfma2(a, u2bf2(e.y), ac1);
                    ac2 = __hfma2(a, u2bf2(e.z), ac2);
                    ac3 = __hfma2(a, u2bf2(e.w), ac3);
                }
            }
            facc[0] += __low2float(ac0); facc[1] += __high2float(ac0);
            facc[2] += __low2float(ac1); facc[3] += __high2float(ac1);
            facc[4] += __low2float(ac2); facc[5] += __high2float(ac2);
            facc[6] += __low2float(ac3); facc[7] += __high2float(ac3);
        }
        // ---- register-resident rows: 2 chunks x 12 ----
        #pragma unroll
        for (int c = 0; c < 2; ++c) {
            __nv_bfloat162 ac0 = z, ac1 = z, ac2 = z, ac3 = z;
            const int i0 = iBase + SMG + c * 12, m0 = c * 12;
            #pragma unroll
            for (int u = 0; u < 3; ++u) {
                uint4 av = *reinterpret_cast<const uint4*>(sA + i0 + u * 4);
                unsigned avv[4] = {av.x, av.y, av.z, av.w};
                #pragma unroll
                for (int r = 0; r < 4; ++r) {
                    uint4 e = eReg[m0 + u * 4 + r];
                    __nv_bfloat162 a = u2bf2(avv[r]);
                    ac0 = __hfma2(a, u2bf2(e.x), ac0);
                    ac1 = __hfma2(a, u2bf2(e.y), ac1);
                    ac2 = __hfma2(a, u2bf2(e.z), ac2);
                    ac3 = __hfma2(a, u2bf2(e.w), ac3);
                }
            }
            facc[0] += __low2float(ac0); facc[1] += __high2float(ac0);
            facc[2] += __low2float(ac1); facc[3] += __high2float(ac1);
            facc[4] += __low2float(ac2); facc[5] += __high2float(ac2);
            facc[6] += __low2float(ac3); facc[7] += __high2float(ac3);
        }

        // ---- cross-i-group reduction ----
        {
            float2* ps = reinterpret_cast<float2*>(sP + ig * JH + oct * 8);
            ps[0] = make_float2(facc[0], facc[1]);
            ps[1] = make_float2(facc[2], facc[3]);
            ps[2] = make_float2(facc[4], facc[5]);
            ps[3] = make_float2(facc[6], facc[7]);
        }
        __syncthreads();
        float p = 0.f;
        #pragma unroll
        for (int q = 0; q < 8; ++q) p += sP[q * JH + t];

        // raw alpha' for own j (log2-offset domain)
        float raw = p * exp2f((w + sCf[t]) * LOG2E);

        // ship raw to peer (double-buffered slot)
        st_cluster_f32(recvPeer + (unsigned)(slot * 264 + t) * 4u, raw);

        // local half-max
        float m = raw;
        #pragma unroll
        for (int o = 16; o > 0; o >>= 1) m = fmaxf(m, __shfl_xor_sync(0xffffffffu, m, o));
        if (oct == 0) sRed[ig] = m;
        __syncthreads();
        float localM = sRed[0];
        #pragma unroll
        for (int k = 1; k < 8; ++k) localM = fmaxf(localM, sRed[k]);
        if (t == 0) st_cluster_f32(recvPeer + (unsigned)(slot * 264 + 256) * 4u, localM);

        CLUSTER_SYNC();   // release/acquire: peer's raw + max now visible

        float recvM = sRecv[slot * 264 + 256];
        float M2 = fmaxf(fmaxf(localM, recvM), 1e-30f);
        int   m2  = (__float_as_int(M2) >> 23) - 127;       // exact pow2 renorm
        float scl = __int_as_float((127 - m2) << 23);
        E2 += (float)m2;
        float finO = raw * scl;
        float finP = sRecv[slot * 264 + t] * scl;
        sA[rank * JH + t]       = __bfloat162bfloat162(__float2bfloat16(finO));
        sA[(rank ^ 1) * JH + t] = __bfloat162bfloat162(__float2bfloat16(finP));
        finSum = finO + finP;
        __syncthreads();
        slot ^= 1;
    }

    float total = blkSum<8>(finSum, sRed);
    if (rank == 0 && t == 0) out[b] = logf(total) + E2 * LN2;
    CLUSTER_SYNC();   // no CTA exits while peer DSMEM traffic could be in flight
}

// ---------------- launch -------------------------------------------------------
extern "C" void kernel_launch(void* const* d_in, const int* in_sizes, int n_in,
                              void* d_out, int out_size) {
    const int*   obs   = (const int*)d_in[0];
    const float* ST    = (const float*)d_in[1];
    const float* OT    = (const float*)d_in[2];
    const float* prior = (const float*)d_in[3];
    float* out = (float*)d_out;

    cudaFuncSetAttribute(k_forward, cudaFuncAttributeMaxDynamicSharedMemorySize,
                         SMEM_TOTAL);

    k_rowlse<<<S, 256>>>(ST);
    k_colmax<<<4, 128>>>(ST);
    k_expT<<<S, 256>>>(ST);
    k_obslse<<<S, 256>>>(OT);
    k_prior<<<1, S>>>(prior);
    k_forward<<<BATCH * 2, NTHREADS, SMEM_TOTAL>>>(obs, OT, out);
}

// round 8
// speedup vs baseline: 2.0376x; 1.1173x over previous
#include <cuda_runtime.h>
#include <cuda_bf16.h>
#include <cstdint>
#include <math.h>

#define S      512
#define BATCH  64
#define TLEN   1024
#define OBS_N  32000
#define NTHREADS 256
#define JH     256              // j-columns per CTA (cluster of 2)
#define SMG    32               // SMEM rows per 64-row i-group
#define SM_ROWS (8 * SMG)       // 256 rows resident in SMEM
#define REG_ROWS 32             // register-resident rows per thread
#define LOG2E 1.4426950408889634f
#define LN2   0.6931471805599453f

// ---------------- device scratch ---------------------------------------------
__device__ float g_lseRow[S];
__device__ float g_mT[S];
__device__ float g_lseObs[S];
__device__ float g_Cfold[S];                 // mT - lseObs
__device__ float g_initAdd[S];               // log_softmax(prior) - lseObs
__device__ __nv_bfloat16 g_expT2[2 * S * JH];  // [rank][i][256]

// ---------------- helpers -----------------------------------------------------
__device__ __forceinline__ __nv_bfloat162 u2bf2(unsigned u) {
    __nv_bfloat162 r; *reinterpret_cast<unsigned*>(&r) = u; return r;
}
__device__ __forceinline__ uint32_t smem_u32(const void* p) {
    uint32_t a;
    asm("{ .reg .u64 t; cvta.to.shared.u64 t, %1; cvt.u32.u64 %0, t; }"
        : "=r"(a) : "l"(p));
    return a;
}
__device__ __forceinline__ uint32_t mapa_u32(uint32_t a, uint32_t rank) {
    uint32_t d;
    asm("mapa.shared::cluster.u32 %0, %1, %2;" : "=r"(d) : "r"(a), "r"(rank));
    return d;
}
__device__ __forceinline__ void st_cluster_f32(uint32_t a, float v) {
    asm volatile("st.shared::cluster.f32 [%0], %1;" :: "r"(a), "f"(v) : "memory");
}
__device__ __forceinline__ void mbar_init(uint32_t a, unsigned cnt) {
    asm volatile("mbarrier.init.shared.b64 [%0], %1;" :: "r"(a), "r"(cnt) : "memory");
}
// release.cluster arrive on a peer (mapa'd) barrier: orders this thread's
// prior st.shared::cluster stores before the arrival.
__device__ __forceinline__ void mbar_arrive_cluster(uint32_t a) {
    asm volatile("mbarrier.arrive.release.cluster.shared::cluster.b64 _, [%0];"
                 :: "r"(a) : "memory");
}
// acquire.cluster parity wait on a LOCAL barrier.
__device__ __forceinline__ void mbar_wait_cluster(uint32_t a, unsigned parity) {
    unsigned done;
    asm volatile(
        "{\n\t.reg .pred p;\n\t"
        "mbarrier.try_wait.parity.acquire.cluster.shared::cta.b64 p, [%1], %2;\n\t"
        "selp.b32 %0, 1, 0, p;\n\t}"
        : "=r"(done) : "r"(a), "r"(parity) : "memory");
    if (!done) {
        asm volatile(
            "{\n\t.reg .pred P1;\n\t"
            "WAIT_LOOP_%=:\n\t"
            "mbarrier.try_wait.parity.acquire.cluster.shared::cta.b64 P1, [%0], %1, 0x989680;\n\t"
            "@P1 bra.uni WAIT_DONE_%=;\n\t"
            "bra.uni WAIT_LOOP_%=;\n\t"
            "WAIT_DONE_%=:\n\t}"
            :: "r"(a), "r"(parity) : "memory");
    }
}
#define CLUSTER_SYNC() do { \
    asm volatile("barrier.cluster.arrive.aligned;" ::: "memory"); \
    asm volatile("barrier.cluster.wait.aligned;"   ::: "memory"); \
} while (0)

template <int NW>
__device__ __forceinline__ float blkMax(float v, float* red) {
    #pragma unroll
    for (int o = 16; o > 0; o >>= 1) v = fmaxf(v, __shfl_xor_sync(0xffffffffu, v, o));
    int w = threadIdx.x >> 5;
    if ((threadIdx.x & 31) == 0) red[w] = v;
    __syncthreads();
    float m = red[0];
    #pragma unroll
    for (int k = 1; k < NW; ++k) m = fmaxf(m, red[k]);
    __syncthreads();
    return m;
}
template <int NW>
__device__ __forceinline__ float blkSum(float v, float* red) {
    #pragma unroll
    for (int o = 16; o > 0; o >>= 1) v += __shfl_xor_sync(0xffffffffu, v, o);
    int w = threadIdx.x >> 5;
    if ((threadIdx.x & 31) == 0) red[w] = v;
    __syncthreads();
    float m = 0.f;
    #pragma unroll
    for (int k = 0; k < NW; ++k) m += red[k];
    __syncthreads();
    return m;
}

// ---------------- precompute kernels ------------------------------------------
__global__ void k_rowlse(const float* __restrict__ ST) {
    __shared__ float red[8];
    int i = blockIdx.x, t = threadIdx.x;
    float x0 = ST[i * S + t], x1 = ST[i * S + t + 256];
    float M = blkMax<8>(fmaxf(x0, x1), red);
    float Ssum = blkSum<8>(expf(x0 - M) + expf(x1 - M), red);
    if (t == 0) g_lseRow[i] = M + logf(Ssum);
}
__global__ void k_colmax(const float* __restrict__ ST) {
    int j = blockIdx.x * blockDim.x + threadIdx.x;
    float m = -1e30f;
    for (int i = 0; i < S; ++i) m = fmaxf(m, ST[i * S + j] - g_lseRow[i]);
    g_mT[j] = m;
}
__global__ void k_expT(const float* __restrict__ ST) {
    int i = blockIdx.x;
    float l = g_lseRow[i];
    for (int j = threadIdx.x; j < S; j += 256) {
        float v = expf(ST[i * S + j] - l - g_mT[j]);
        int rank = j >> 8, c = j & 255;
        g_expT2[((size_t)rank * S + i) * JH + c] = __float2bfloat16(v);
    }
}
__global__ void k_obslse(const float* __restrict__ OT) {
    __shared__ float red[8];
    int s = blockIdx.x, t = threadIdx.x;
    const float* row = OT + (size_t)s * OBS_N;
    float m = -1e30f;
    for (int k = t; k < OBS_N; k += 256) m = fmaxf(m, row[k]);
    float M = blkMax<8>(m, red);
    float acc = 0.f;
    for (int k = t; k < OBS_N; k += 256) acc += expf(row[k] - M);
    float Ssum = blkSum<8>(acc, red);
    if (t == 0) {
        float lse = M + logf(Ssum);
        g_lseObs[s] = lse;
        g_Cfold[s]  = g_mT[s] - lse;
    }
}
__global__ void k_prior(const float* __restrict__ prior) {
    __shared__ float red[16];
    int t = threadIdx.x;
    float p = prior[t];
    float M = blkMax<16>(p, red);
    float Ssum = blkSum<16>(expf(p - M), red);
    float lse = M + logf(Ssum);
    g_initAdd[t] = (p - lse) - g_lseObs[t];
}

// ---------------- forward kernel (cluster of 2, mbarrier exchange) ------------
// SMEM (bytes):
//  [0,131072)        sT    bf16 [256][256] (rows k<32 of each 64-row i-group)
//  [131072,139264)   sP    f32 [8][256]
//  [139264,141312)   sA    bf16x2 [512] (replicated halves)
//  [141312,142336)   sCf   f32 [256] (own j-half)
//  [142336,144512)   sRecv f32 [2][272] ([0..255]=raw, [256..263]=warp maxes)
//  [144512,148608)   sOb   int [1024]
//  [148608,148640)   sRed  f32 [8]
//  [148640,148656)   mbar  2 x u64
#define OFF_P    131072
#define OFF_A    139264
#define OFF_CF   141312
#define OFF_RECV 142336
#define OFF_OB   144512
#define OFF_RED  148608
#define OFF_MB   148640
#define SMEM_TOTAL 148736
#define RSTRIDE 272

__global__ void __launch_bounds__(NTHREADS, 1) __cluster_dims__(2, 1, 1)
k_forward(const int* __restrict__ obs, const float* __restrict__ OT,
          float* __restrict__ out) {
    extern __shared__ char smem[];
    __nv_bfloat16*  sT   = reinterpret_cast<__nv_bfloat16*>(smem);
    float*          sP   = reinterpret_cast<float*>(smem + OFF_P);
    __nv_bfloat162* sA   = reinterpret_cast<__nv_bfloat162*>(smem + OFF_A);
    float*          sCf  = reinterpret_cast<float*>(smem + OFF_CF);
    float*          sRecv= reinterpret_cast<float*>(smem + OFF_RECV);
    int*            sOb  = reinterpret_cast<int*>(smem + OFF_OB);
    float*          sRed = reinterpret_cast<float*>(smem + OFF_RED);

    const int t    = threadIdx.x;
    const int rank = blockIdx.x & 1;
    const int b    = blockIdx.x >> 1;
    const int ig   = t >> 5, oct = t & 31;     // 8 i-groups x 32 j-octs

    const __nv_bfloat16* gT = g_expT2 + (size_t)rank * S * JH;

    const uint32_t mbLoc  = smem_u32(smem + OFF_MB);
    const uint32_t mbPeer = mapa_u32(mbLoc, (uint32_t)(rank ^ 1));
    const uint32_t recvPeer = mapa_u32(smem_u32(sRecv), (uint32_t)(rank ^ 1));

    if (t == 0) { mbar_init(mbLoc, NTHREADS); mbar_init(mbLoc + 8, NTHREADS); }

    // one-time: SMEM copy (SMEM row g*32+k <- expT half row g*64+k, k<32)
    {
        const uint4* src = reinterpret_cast<const uint4*>(gT);   // 32 uint4/row
        uint4* dst = reinterpret_cast<uint4*>(sT);
        for (int idx = t; idx < SM_ROWS * 32; idx += NTHREADS) {
            int r = idx >> 5, c = idx & 31;
            int g = r >> 5, k = r & 31;
            dst[idx] = src[(g * 64 + k) * 32 + c];
        }
    }
    for (int k = t; k < JH; k += NTHREADS)   sCf[k] = g_Cfold[rank * JH + k];
    for (int k = t; k < TLEN; k += NTHREADS) sOb[k] = obs[b * TLEN + k];

    // register-resident rows: expT half rows ig*64+32 .. ig*64+63 (step-invariant)
    uint4 eReg[REG_ROWS];
    {
        const int rb = ig * 64 + SMG;
        #pragma unroll
        for (int m = 0; m < REG_ROWS; ++m)
            eReg[m] = __ldg(reinterpret_cast<const uint4*>(
                gT + (size_t)(rb + m) * JH + oct * 8));
    }
    __syncthreads();

    // init: alpha0 over full 512 (redundant in both CTAs -> identical E2 track)
    float E2;
    {
        int o0 = sOb[0];
        int j0 = 2 * t;
        float a0 = __ldg(OT + (size_t)j0 * OBS_N + o0)       + g_initAdd[j0];
        float a1 = __ldg(OT + (size_t)(j0 + 1) * OBS_N + o0) + g_initAdd[j0 + 1];
        float M = blkMax<8>(fmaxf(a0, a1), sRed);
        E2 = M * LOG2E;
        sA[j0]     = __bfloat162bfloat162(__float2bfloat16(exp2f((a0 - M) * LOG2E)));
        sA[j0 + 1] = __bfloat162bfloat162(__float2bfloat16(exp2f((a1 - M) * LOG2E)));
    }
    CLUSTER_SYNC();   // mbarrier inits + sA visible before any peer arrive

    const int iBase  = ig * 64;
    const int srBase = ig * SMG;
    const __nv_bfloat162 z = __float2bfloat162_rn(0.f);
    float finSum = 0.f;
    int slot = 0;
    int ph[2] = {0, 0};

    #pragma unroll 1
    for (int step = 1; step <= TLEN; ++step) {
        const int ot = (step < TLEN) ? sOb[step] : 0;            // terminal obs 0
        const float w = __ldg(OT + (size_t)(rank * JH + t) * OBS_N + ot);

        float facc[8];
        #pragma unroll
        for (int k = 0; k < 8; ++k) facc[k] = 0.f;

        // ---- SMEM-resident rows: 2 chunks x 16 ----
        #pragma unroll
        for (int c = 0; c < 2; ++c) {
            __nv_bfloat162 ac0 = z, ac1 = z, ac2 = z, ac3 = z;
            const int i0 = iBase + c * 16, s0 = srBase + c * 16;
            #pragma unroll
            for (int u = 0; u < 4; ++u) {
                uint4 av = *reinterpret_cast<const uint4*>(sA + i0 + u * 4);
                unsigned avv[4] = {av.x, av.y, av.z, av.w};
                #pragma unroll
                for (int r = 0; r < 4; ++r) {
                    uint4 e = *reinterpret_cast<const uint4*>(
                        sT + (size_t)(s0 + u * 4 + r) * JH + oct * 8);
                    __nv_bfloat162 a = u2bf2(avv[r]);
                    ac0 = __hfma2(a, u2bf2(e.x), ac0);
                    ac1 = __hfma2(a, u2bf2(e.y), ac1);
                    ac2 = __hfma2(a, u2bf2(e.z), ac2);
                    ac3 = __hfma2(a, u2bf2(e.w), ac3);
                }
            }
            facc[0] += __low2float(ac0); facc[1] += __high2float(ac0);
            facc[2] += __low2float(ac1); facc[3] += __high2float(ac1);
            facc[4] += __low2float(ac2); facc[5] += __high2float(ac2);
            facc[6] += __low2float(ac3); facc[7] += __high2float(ac3);
        }
        // ---- register-resident rows: 2 chunks x 16 ----
        #pragma unroll
        for (int c = 0; c < 2; ++c) {
            __nv_bfloat162 ac0 = z, ac1 = z, ac2 = z, ac3 = z;
            const int i0 = iBase + SMG + c * 16, m0 = c * 16;
            #pragma unroll
            for (int u = 0; u < 4; ++u) {
                uint4 av = *reinterpret_cast<const uint4*>(sA + i0 + u * 4);
                unsigned avv[4] = {av.x, av.y, av.z, av.w};
                #pragma unroll
                for (int r = 0; r < 4; ++r) {
                    uint4 e = eReg[m0 + u * 4 + r];
                    __nv_bfloat162 a = u2bf2(avv[r]);
                    ac0 = __hfma2(a, u2bf2(e.x), ac0);
                    ac1 = __hfma2(a, u2bf2(e.y), ac1);
                    ac2 = __hfma2(a, u2bf2(e.z), ac2);
                    ac3 = __hfma2(a, u2bf2(e.w), ac3);
                }
            }
            facc[0] += __low2float(ac0); facc[1] += __high2float(ac0);
            facc[2] += __low2float(ac1); facc[3] += __high2float(ac1);
            facc[4] += __low2float(ac2); facc[5] += __high2float(ac2);
            facc[6] += __low2float(ac3); facc[7] += __high2float(ac3);
        }

        // ---- cross-i-group reduction ----
        {
            float2* ps = reinterpret_cast<float2*>(sP + ig * JH + oct * 8);
            ps[0] = make_float2(facc[0], facc[1]);
            ps[1] = make_float2(facc[2], facc[3]);
            ps[2] = make_float2(facc[4], facc[5]);
            ps[3] = make_float2(facc[6], facc[7]);
        }
        __syncthreads();
        float p = 0.f;
        #pragma unroll
        for (int q = 0; q < 8; ++q) p += sP[q * JH + t];

        // raw alpha' for own j (log2-offset domain)
        float raw = p * exp2f((w + sCf[t]) * LOG2E);

        // ship raw to peer (double-buffered slot), then warp max, then arrive
        const unsigned rbase = (unsigned)(slot * RSTRIDE);
        st_cluster_f32(recvPeer + (rbase + t) * 4u, raw);
        float m = raw;
        #pragma unroll
        for (int o = 16; o > 0; o >>= 1)
            m = fmaxf(m, __shfl_xor_sync(0xffffffffu, m, o));
        if (oct == 0) {
            st_cluster_f32(recvPeer + (rbase + 256 + ig) * 4u, m);
            sRed[ig] = m;
        }
        mbar_arrive_cluster(mbPeer + slot * 8);   // release: orders stores above
        __syncthreads();                          // orders local sRed stores
        mbar_wait_cluster(mbLoc + slot * 8, (unsigned)ph[slot]);
        ph[slot] ^= 1;

        // global max from 8 local + 8 peer warp maxes (redundant per thread)
        float M2 = 1e-30f;
        #pragma unroll
        for (int k = 0; k < 8; ++k) M2 = fmaxf(M2, sRed[k]);
        #pragma unroll
        for (int k = 0; k < 8; ++k) M2 = fmaxf(M2, sRecv[rbase + 256 + k]);
        int   m2  = (__float_as_int(M2) >> 23) - 127;       // exact pow2 renorm
        float scl = __int_as_float((127 - m2) << 23);
        E2 += (float)m2;
        float finO = raw * scl;
        float finP = sRecv[rbase + t] * scl;
        sA[rank * JH + t]       = __bfloat162bfloat162(__float2bfloat16(finO));
        sA[(rank ^ 1) * JH + t] = __bfloat162bfloat162(__float2bfloat16(finP));
        finSum = finO + finP;
        __syncthreads();
        slot ^= 1;
    }

    float total = blkSum<8>(finSum, sRed);
    if (rank == 0 && t == 0) out[b] = logf(total) + E2 * LN2;
    CLUSTER_SYNC();   // no CTA exits while peer DSMEM traffic could be in flight
}

// ---------------- launch -------------------------------------------------------
extern "C" void kernel_launch(void* const* d_in, const int* in_sizes, int n_in,
                              void* d_out, int out_size) {
    const int*   obs   = (const int*)d_in[0];
    const float* ST    = (const float*)d_in[1];
    const float* OT    = (const float*)d_in[2];
    const float* prior = (const float*)d_in[3];
    float* out = (float*)d_out;

    cudaFuncSetAttribute(k_forward, cudaFuncAttributeMaxDynamicSharedMemorySize,
                         SMEM_TOTAL);

    k_rowlse<<<S, 256>>>(ST);
    k_colmax<<<4, 128>>>(ST);
    k_expT<<<S, 256>>>(ST);
    k_obslse<<<S, 256>>>(OT);
    k_prior<<<1, S>>>(prior);
    k_forward<<<BATCH * 2, NTHREADS, SMEM_TOTAL>>>(obs, OT, out);
}

// round 10
// speedup vs baseline: 2.2023x; 1.0808x over previous
#include <cuda_runtime.h>
#include <cuda_bf16.h>
#include <cstdint>
#include <math.h>

#define S      512
#define BATCH  64
#define TLEN   1024
#define OBS_N  32000
#define NTHREADS 256
#define JH     256              // j-columns per CTA (cluster of 2)
#define LOG2E 1.4426950408889634f
#define LN2   0.6931471805599453f

// ---------------- device scratch ---------------------------------------------
__device__ float g_lseRow[S];
__device__ float g_mT[S];
__device__ float g_lseObs[S];
__device__ float g_Cfold[S];                 // mT - lseObs
__device__ float g_initAdd[S];               // log_softmax(prior) - lseObs
__device__ __nv_bfloat16 g_expT2[2 * S * JH];  // [rank][i][256]

// ---------------- helpers -----------------------------------------------------
__device__ __forceinline__ float ex2_fast(float x) {   // MUFU.EX2
    float r;
    asm("ex2.approx.ftz.f32 %0, %1;" : "=f"(r) : "f"(x));
    return r;
}
__device__ __forceinline__ __nv_bfloat162 u2bf2(unsigned u) {
    __nv_bfloat162 r; *reinterpret_cast<unsigned*>(&r) = u; return r;
}
__device__ __forceinline__ uint32_t smem_u32(const void* p) {
    uint32_t a;
    asm("{ .reg .u64 t; cvta.to.shared.u64 t, %1; cvt.u32.u64 %0, t; }"
        : "=r"(a) : "l"(p));
    return a;
}
__device__ __forceinline__ uint32_t mapa_u32(uint32_t a, uint32_t rank) {
    uint32_t d;
    asm("mapa.shared::cluster.u32 %0, %1, %2;" : "=r"(d) : "r"(a), "r"(rank));
    return d;
}
__device__ __forceinline__ void st_cluster_f32(uint32_t a, float v) {
    asm volatile("st.shared::cluster.f32 [%0], %1;" :: "r"(a), "f"(v) : "memory");
}
__device__ __forceinline__ void mbar_init(uint32_t a, unsigned cnt) {
    asm volatile("mbarrier.init.shared.b64 [%0], %1;" :: "r"(a), "r"(cnt) : "memory");
}
__device__ __forceinline__ void mbar_arrive_cluster(uint32_t a) {
    asm volatile("mbarrier.arrive.release.cluster.shared::cluster.b64 _, [%0];"
                 :: "r"(a) : "memory");
}
__device__ __forceinline__ void mbar_wait_cluster(uint32_t a, unsigned parity) {
    unsigned done;
    asm volatile(
        "{\n\t.reg .pred p;\n\t"
        "mbarrier.try_wait.parity.acquire.cluster.shared::cta.b64 p, [%1], %2;\n\t"
        "selp.b32 %0, 1, 0, p;\n\t}"
        : "=r"(done) : "r"(a), "r"(parity) : "memory");
    if (!done) {
        asm volatile(
            "{\n\t.reg .pred P1;\n\t"
            "WAIT_LOOP_%=:\n\t"
            "mbarrier.try_wait.parity.acquire.cluster.shared::cta.b64 P1, [%0], %1, 0x989680;\n\t"
            "@P1 bra.uni WAIT_DONE_%=;\n\t"
            "bra.uni WAIT_LOOP_%=;\n\t"
            "WAIT_DONE_%=:\n\t}"
            :: "r"(a), "r"(parity) : "memory");
    }
}
#define CLUSTER_SYNC() do { \
    asm volatile("barrier.cluster.arrive.aligned;" ::: "memory"); \
    asm volatile("barrier.cluster.wait.aligned;"   ::: "memory"); \
} while (0)

template <int NW>
__device__ __forceinline__ float blkMax(float v, float* red) {
    #pragma unroll
    for (int o = 16; o > 0; o >>= 1) v = fmaxf(v, __shfl_xor_sync(0xffffffffu, v, o));
    int w = threadIdx.x >> 5;
    if ((threadIdx.x & 31) == 0) red[w] = v;
    __syncthreads();
    float m = red[0];
    #pragma unroll
    for (int k = 1; k < NW; ++k) m = fmaxf(m, red[k]);
    __syncthreads();
    return m;
}
template <int NW>
__device__ __forceinline__ float blkSum(float v, float* red) {
    #pragma unroll
    for (int o = 16; o > 0; o >>= 1) v += __shfl_xor_sync(0xffffffffu, v, o);
    int w = threadIdx.x >> 5;
    if ((threadIdx.x & 31) == 0) red[w] = v;
    __syncthreads();
    float m = 0.f;
    #pragma unroll
    for (int k = 0; k < NW; ++k) m += red[k];
    __syncthreads();
    return m;
}

// ---------------- precompute kernels ------------------------------------------
__global__ void k_rowlse(const float* __restrict__ ST) {
    __shared__ float red[8];
    int i = blockIdx.x, t = threadIdx.x;
    float x0 = ST[i * S + t], x1 = ST[i * S + t + 256];
    float M = blkMax<8>(fmaxf(x0, x1), red);
    float Ssum = blkSum<8>(expf(x0 - M) + expf(x1 - M), red);
    if (t == 0) g_lseRow[i] = M + logf(Ssum);
}
__global__ void k_colmax(const float* __restrict__ ST) {
    int j = blockIdx.x * blockDim.x + threadIdx.x;
    float m = -1e30f;
    for (int i = 0; i < S; ++i) m = fmaxf(m, ST[i * S + j] - g_lseRow[i]);
    g_mT[j] = m;
}
__global__ void k_expT(const float* __restrict__ ST) {
    int i = blockIdx.x;
    float l = g_lseRow[i];
    for (int j = threadIdx.x; j < S; j += 256) {
        float v = expf(ST[i * S + j] - l - g_mT[j]);
        int rank = j >> 8, c = j & 255;
        g_expT2[((size_t)rank * S + i) * JH + c] = __float2bfloat16(v);
    }
}
__global__ void k_obslse(const float* __restrict__ OT) {
    __shared__ float red[8];
    int s = blockIdx.x, t = threadIdx.x;
    const float* row = OT + (size_t)s * OBS_N;
    float m = -1e30f;
    for (int k = t; k < OBS_N; k += 256) m = fmaxf(m, row[k]);
    float M = blkMax<8>(m, red);
    float acc = 0.f;
    for (int k = t; k < OBS_N; k += 256) acc += expf(row[k] - M);
    float Ssum = blkSum<8>(acc, red);
    if (t == 0) {
        float lse = M + logf(Ssum);
        g_lseObs[s] = lse;
        g_Cfold[s]  = g_mT[s] - lse;
    }
}
__global__ void k_prior(const float* __restrict__ prior) {
    __shared__ float red[16];
    int t = threadIdx.x;
    float p = prior[t];
    float M = blkMax<16>(p, red);
    float Ssum = blkSum<16>(expf(p - M), red);
    float lse = M + logf(Ssum);
    g_initAdd[t] = (p - lse) - g_lseObs[t];
}

// ---------------- forward kernel ------------------------------------------------
// Step order: A(matvec own-half i) | B(wait peer, fold m2, sA_peer) | C(matvec
// peer-half i) | D(sP reduce) | E(raw, ship, sA_own).  DSMEM latency hidden under A.
// Each warp w owns 64 i-rows: 32 own-half (16 SMEM + 16 reg) + 32 peer-half (same).
// sT row (2w+h)*16+k  <->  expT-half abs row halfbase(h) + w*32 + k      (k<16)
// eReg[h*16+m]        <->  abs row halfbase(h) + w*32 + 16 + m
//
// SMEM (bytes):
//  [0,131072)        sT    bf16 [256][256]
//  [131072,139264)   sP    f32 [8][256]
//  [139264,141312)   sA    bf16x2 [512] (RAW alpha, replicated halves)
//  [141312,142336)   sCf   f32 [256]
//  [142336,144512)   sRecv f32 [2][272] ([0..255]=raw, [256..263]=warp maxes)
//  [144512,148608)   sOb   int [1024]
//  [148608,148640)   sRed  f32 [8]
//  [148640,148656)   mbar  2 x u64
#define OFF_P    131072
#define OFF_A    139264
#define OFF_CF   141312
#define OFF_RECV 142336
#define OFF_OB   144512
#define OFF_RED  148608
#define OFF_MB   148640
#define SMEM_TOTAL 148736
#define RSTRIDE 272

__global__ void __launch_bounds__(NTHREADS, 1) __cluster_dims__(2, 1, 1)
k_forward(const int* __restrict__ obs, const float* __restrict__ OT,
          float* __restrict__ out) {
    extern __shared__ char smem[];
    __nv_bfloat16*  sT   = reinterpret_cast<__nv_bfloat16*>(smem);
    float*          sP   = reinterpret_cast<float*>(smem + OFF_P);
    __nv_bfloat162* sA   = reinterpret_cast<__nv_bfloat162*>(smem + OFF_A);
    float*          sCf  = reinterpret_cast<float*>(smem + OFF_CF);
    float*          sRecv= reinterpret_cast<float*>(smem + OFF_RECV);
    int*            sOb  = reinterpret_cast<int*>(smem + OFF_OB);
    float*          sRed = reinterpret_cast<float*>(smem + OFF_RED);

    const int t    = threadIdx.x;
    const int rank = blockIdx.x & 1;
    const int b    = blockIdx.x >> 1;
    const int ig   = t >> 5, oct = t & 31;

    const __nv_bfloat16* gT = g_expT2 + (size_t)rank * S * JH;

    const uint32_t mbLoc    = smem_u32(smem + OFF_MB);
    const uint32_t mbPeer   = mapa_u32(mbLoc, (uint32_t)(rank ^ 1));
    const uint32_t recvPeer = mapa_u32(smem_u32(sRecv), (uint32_t)(rank ^ 1));

    if (t == 0) { mbar_init(mbLoc, NTHREADS); mbar_init(mbLoc + 8, NTHREADS); }

    const int ownBase  = rank * JH;          // abs i base of own half
    const int peerBase = (rank ^ 1) * JH;

    // one-time SMEM copy: sT row (2w+h)*16+k <- abs row halfbase(h)+w*32+k
    {
        const uint4* src = reinterpret_cast<const uint4*>(gT);   // 32 uint4/row
        uint4* dst = reinterpret_cast<uint4*>(sT);
        for (int idx = t; idx < 256 * 32; idx += NTHREADS) {
            int r = idx >> 5, c = idx & 31;
            int w = r >> 5, h = (r >> 4) & 1, k = r & 15;
            int iabs = (h ? peerBase : ownBase) + w * 32 + k;
            dst[idx] = src[iabs * 32 + c];
        }
    }
    for (int k = t; k < JH; k += NTHREADS)   sCf[k] = g_Cfold[ownBase + k];
    for (int k = t; k < TLEN; k += NTHREADS) sOb[k] = obs[b * TLEN + k];

    // register-resident rows (step-invariant): eReg[h*16+m] <- abs ig*32+16+m of half h
    uint4 eReg[32];
    {
        #pragma unroll
        for (int m = 0; m < 16; ++m)
            eReg[m] = __ldg(reinterpret_cast<const uint4*>(
                gT + (size_t)(ownBase + ig * 32 + 16 + m) * JH + oct * 8));
        #pragma unroll
        for (int m = 0; m < 16; ++m)
            eReg[16 + m] = __ldg(reinterpret_cast<const uint4*>(
                gT + (size_t)(peerBase + ig * 32 + 16 + m) * JH + oct * 8));
    }
    __syncthreads();

    // ---- init: raw0 for ALL 512 (both CTAs identically), ship own half ----
    float E2;
    float rawOwn;                // this thread's own-half raw (j = ownBase + t)
    {
        int o0 = sOb[0];
        int jO = ownBase + t, jP = peerBase + t;
        float aO = __ldg(OT + (size_t)jO * OBS_N + o0) + g_initAdd[jO];
        float aP = __ldg(OT + (size_t)jP * OBS_N + o0) + g_initAdd[jP];
        float M = blkMax<8>(fmaxf(aO, aP), sRed);
        E2 = M * LOG2E;
        rawOwn = ex2_fast((aO - M) * LOG2E);
        float rawP = ex2_fast((aP - M) * LOG2E);
        sA[jO] = __bfloat162bfloat162(__float2bfloat16(rawOwn));
        sA[jP] = __bfloat162bfloat162(__float2bfloat16(rawP));
        // emulate E(0): ship own raw + warp maxes on slot 0
        st_cluster_f32(recvPeer + (unsigned)t * 4u, rawOwn);
        float m = rawOwn;
        #pragma unroll
        for (int o = 16; o > 0; o >>= 1)
            m = fmaxf(m, __shfl_xor_sync(0xffffffffu, m, o));
        if (oct == 0) {
            st_cluster_f32(recvPeer + (unsigned)(256 + ig) * 4u, m);
            sRed[ig] = m;
        }
    }
    CLUSTER_SYNC();   // mbarrier inits + init stores visible before arrivals
    mbar_arrive_cluster(mbPeer);      // slot 0 arrive (after inits are safe)
    __syncthreads();

    const float cf = sCf[t];                       // loop-invariant
    const float* wPtr = OT + (size_t)(ownBase + t) * OBS_N;
    const int sRow0 = (ig * 2) * 16;               // own-half SMEM row base
    const int sRow1 = (ig * 2 + 1) * 16;           // peer-half SMEM row base
    const __nv_bfloat162 z = __float2bfloat162_rn(0.f);

    int slot = 0;
    int ph[2] = {0, 0};
    float scl = 1.f;   // set at B each step

    #pragma unroll 1
    for (int step = 1; step <= TLEN; ++step) {
        const int ot = (step < TLEN) ? sOb[step] : 0;
        const float w = __ldg(wPtr + ot);

        float facc[8];
        #pragma unroll
        for (int k = 0; k < 8; ++k) facc[k] = 0.f;

        // ================= phase A: own-half i (32 rows) =================
        {
            // chunk 0: SMEM rows
            __nv_bfloat162 ac0 = z, ac1 = z, ac2 = z, ac3 = z;
            #pragma unroll
            for (int u = 0; u < 4; ++u) {
                uint4 av = *reinterpret_cast<const uint4*>(sA + ownBase + ig * 32 + u * 4);
                unsigned avv[4] = {av.x, av.y, av.z, av.w};
                #pragma unroll
                for (int r = 0; r < 4; ++r) {
                    uint4 e = *reinterpret_cast<const uint4*>(
                        sT + (size_t)(sRow0 + u * 4 + r) * JH + oct * 8);
                    __nv_bfloat162 a = u2bf2(avv[r]);
                    ac0 = __hfma2(a, u2bf2(e.x), ac0);
                    ac1 = __hfma2(a, u2bf2(e.y), ac1);
                    ac2 = __hfma2(a, u2bf2(e.z), ac2);
                    ac3 = __hfma2(a, u2bf2(e.w), ac3);
                }
            }
            facc[0] += __low2float(ac0); facc[1] += __high2float(ac0);
            facc[2] += __low2float(ac1); facc[3] += __high2float(ac1);
            facc[4] += __low2float(ac2); facc[5] += __high2float(ac2);
            facc[6] += __low2float(ac3); facc[7] += __high2float(ac3);
            // chunk 1: reg rows
            ac0 = z; ac1 = z; ac2 = z; ac3 = z;
            #pragma unroll
            for (int u = 0; u < 4; ++u) {
                uint4 av = *reinterpret_cast<const uint4*>(sA + ownBase + ig * 32 + 16 + u * 4);
                unsigned avv[4] = {av.x, av.y, av.z, av.w};
                #pragma unroll
                for (int r = 0; r < 4; ++r) {
                    uint4 e = eReg[u * 4 + r];
                    __nv_bfloat162 a = u2bf2(avv[r]);
                    ac0 = __hfma2(a, u2bf2(e.x), ac0);
                    ac1 = __hfma2(a, u2bf2(e.y), ac1);
                    ac2 = __hfma2(a, u2bf2(e.z), ac2);
                    ac3 = __hfma2(a, u2bf2(e.w), ac3);
                }
            }
            facc[0] += __low2float(ac0); facc[1] += __high2float(ac0);
            facc[2] += __low2float(ac1); facc[3] += __high2float(ac1);
            facc[4] += __low2float(ac2); facc[5] += __high2float(ac2);
            facc[6] += __low2float(ac3); facc[7] += __high2float(ac3);
        }

        // ================= phase B: consume peer exchange ================
        mbar_wait_cluster(mbLoc + slot * 8, (unsigned)ph[slot]);
        ph[slot] ^= 1;
        {
            const unsigned rbase = (unsigned)(slot * RSTRIDE);
            float M2 = 1e-30f;
            #pragma unroll
            for (int k = 0; k < 8; ++k) M2 = fmaxf(M2, sRed[k]);
            #pragma unroll
            for (int k = 0; k < 8; ++k) M2 = fmaxf(M2, sRecv[rbase + 256 + k]);
            int m2 = (__float_as_int(M2) >> 23) - 127;
            scl = __int_as_float((127 - m2) << 23);     // 2^-m2, exact
            E2 += (float)m2;
            sA[peerBase + t] =
                __bfloat162bfloat162(__float2bfloat16(sRecv[rbase + t]));
        }
        __syncthreads();

        // ================= phase C: peer-half i (32 rows) ================
        {
            __nv_bfloat162 ac0 = z, ac1 = z, ac2 = z, ac3 = z;
            #pragma unroll
            for (int u = 0; u < 4; ++u) {
                uint4 av = *reinterpret_cast<const uint4*>(sA + peerBase + ig * 32 + u * 4);
                unsigned avv[4] = {av.x, av.y, av.z, av.w};
                #pragma unroll
                for (int r = 0; r < 4; ++r) {
                    uint4 e = *reinterpret_cast<const uint4*>(
                        sT + (size_t)(sRow1 + u * 4 + r) * JH + oct * 8);
                    __nv_bfloat162 a = u2bf2(avv[r]);
                    ac0 = __hfma2(a, u2bf2(e.x), ac0);
                    ac1 = __hfma2(a, u2bf2(e.y), ac1);
                    ac2 = __hfma2(a, u2bf2(e.z), ac2);
                    ac3 = __hfma2(a, u2bf2(e.w), ac3);
                }
            }
            facc[0] += __low2float(ac0); facc[1] += __high2float(ac0);
            facc[2] += __low2float(ac1); facc[3] += __high2float(ac1);
            facc[4] += __low2float(ac2); facc[5] += __high2float(ac2);
            facc[6] += __low2float(ac3); facc[7] += __high2float(ac3);
            ac0 = z; ac1 = z; ac2 = z; ac3 = z;
            #pragma unroll
            for (int u = 0; u < 4; ++u) {
                uint4 av = *reinterpret_cast<const uint4*>(sA + peerBase + ig * 32 + 16 + u * 4);
                unsigned avv[4] = {av.x, av.y, av.z, av.w};
                #pragma unroll
                for (int r = 0; r < 4; ++r) {
                    uint4 e = eReg[16 + u * 4 + r];
                    __nv_bfloat162 a = u2bf2(avv[r]);
                    ac0 = __hfma2(a, u2bf2(e.x), ac0);
                    ac1 = __hfma2(a, u2bf2(e.y), ac1);
                    ac2 = __hfma2(a, u2bf2(e.z), ac2);
                    ac3 = __hfma2(a, u2bf2(e.w), ac3);
                }
            }
            facc[0] += __low2float(ac0); facc[1] += __high2float(ac0);
            facc[2] += __low2float(ac1); facc[3] += __high2float(ac1);
            facc[4] += __low2float(ac2); facc[5] += __high2float(ac2);
            facc[6] += __low2float(ac3); facc[7] += __high2float(ac3);
        }

        // ================= phase D: cross-warp reduction =================
        {
            float2* ps = reinterpret_cast<float2*>(sP + ig * JH + oct * 8);
            ps[0] = make_float2(facc[0], facc[1]);
            ps[1] = make_float2(facc[2], facc[3]);
            ps[2] = make_float2(facc[4], facc[5]);
            ps[3] = make_float2(facc[6], facc[7]);
        }
        __syncthreads();
        float p = 0.f;
        #pragma unroll
        for (int q = 0; q < 8; ++q) p += sP[q * JH + t];

        // ================= phase E: raw, ship, sA_own ====================
        float raw = p * ex2_fast((w + cf) * LOG2E) * scl;
        const int sendSlot = slot ^ 1;
        const unsigned sbase = (unsigned)(sendSlot * RSTRIDE);
        st_cluster_f32(recvPeer + (sbase + t) * 4u, raw);
        float m = raw;
        #pragma unroll
        for (int o = 16; o > 0; o >>= 1)
            m = fmaxf(m, __shfl_xor_sync(0xffffffffu, m, o));
        if (oct == 0) {
            st_cluster_f32(recvPeer + (sbase + 256 + ig) * 4u, m);
            sRed[ig] = m;
        }
        mbar_arrive_cluster(mbPeer + sendSlot * 8);
        sA[ownBase + t] = __bfloat162bfloat162(__float2bfloat16(raw));
        rawOwn = raw;
        __syncthreads();
        slot = sendSlot;
    }

    // final: own raw + peer raw (pending exchange), consistent scale
    mbar_wait_cluster(mbLoc + slot * 8, (unsigned)ph[slot]);
    float finP = sRecv[slot * RSTRIDE + t];
    float total = blkSum<8>(rawOwn + finP, sRed);
    if (rank == 0 && t == 0) out[b] = logf(total) + E2 * LN2;
    CLUSTER_SYNC();
}

// ---------------- launch -------------------------------------------------------
extern "C" void kernel_launch(void* const* d_in, const int* in_sizes, int n_in,
                              void* d_out, int out_size) {
    const int*   obs   = (const int*)d_in[0];
    const float* ST    = (const float*)d_in[1];
    const float* OT    = (const float*)d_in[2];
    const float* prior = (const float*)d_in[3];
    float* out = (float*)d_out;

    cudaFuncSetAttribute(k_forward, cudaFuncAttributeMaxDynamicSharedMemorySize,
                         SMEM_TOTAL);

    k_rowlse<<<S, 256>>>(ST);
    k_colmax<<<4, 128>>>(ST);
    k_expT<<<S, 256>>>(ST);
    k_obslse<<<S, 256>>>(OT);
    k_prior<<<1, S>>>(prior);
    k_forward<<<BATCH * 2, NTHREADS, SMEM_TOTAL>>>(obs, OT, out);
}